// round 15
// baseline (speedup 1.0000x reference)
#include <cuda_runtime.h>
#include <cuda_bf16.h>
#include <cuda_fp16.h>
#include <cstdint>

#define D      128
#define DO2    256
#define NODES  50000
#define LN_EPS 1e-5f

#define CAP    64
#define SPILL_MAX 8192

#define MTILE  64
#define GRID_G ((NODES + MTILE - 1) / MTILE) // 782

#define XROW_W 68
#define XT64_W (64 * XROW_W)            // 4352 words per tile
#define SMEM_GEMM (4 * XT64_W * 4)      // 69632 bytes

#define NKS    8

// Scratch
__device__ int      g_cnt[NODES];
__device__ int2     g_slots[NODES * CAP];
__device__ int4     g_spill[SPILL_MAX];
__device__ int      g_nspill;
// h in fp16: [node][32] uint2 (4 halves each) = 12.8 MB gather table
__device__ uint2    g_h16[NODES * 32];
// support in bf16 hi/lo packed form (written by spmm, L2-hot for gemm)
__device__ uint32_t g_shi[NODES * 64];
__device__ uint32_t g_slo[NODES * 64];
// W fragments, LDG.128-packed: uint4[half][nt(16)][ks(8)][lane(32)]
__device__ uint4    g_Wfrag[2 * 16 * NKS * 32];

// ---------------------------------------------------------------------------
__device__ __forceinline__ uint32_t pack_bf2(__nv_bfloat16 lo, __nv_bfloat16 hi) {
    return (uint32_t)__bfloat16_as_ushort(hi) << 16 | (uint32_t)__bfloat16_as_ushort(lo);
}

__device__ __forceinline__ void mma_bf16(float& d0, float& d1, float& d2, float& d3,
                                         uint32_t a0, uint32_t a1, uint32_t a2, uint32_t a3,
                                         uint32_t b0, uint32_t b1) {
    asm volatile(
        "mma.sync.aligned.m16n8k16.row.col.f32.bf16.bf16.f32 "
        "{%0,%1,%2,%3}, {%4,%5,%6,%7}, {%8,%9}, {%0,%1,%2,%3};"
        : "+f"(d0), "+f"(d1), "+f"(d2), "+f"(d3)
        : "r"(a0), "r"(a1), "r"(a2), "r"(a3), "r"(b0), "r"(b1));
}

__device__ __forceinline__ void split_packs(float4 x, uint2& hi, uint2& lo) {
    __nv_bfloat16 hx = __float2bfloat16_rn(x.x);
    __nv_bfloat16 hy = __float2bfloat16_rn(x.y);
    __nv_bfloat16 hz = __float2bfloat16_rn(x.z);
    __nv_bfloat16 hw = __float2bfloat16_rn(x.w);
    __nv_bfloat16 lx = __float2bfloat16_rn(x.x - __bfloat162float(hx));
    __nv_bfloat16 ly = __float2bfloat16_rn(x.y - __bfloat162float(hy));
    __nv_bfloat16 lz = __float2bfloat16_rn(x.z - __bfloat162float(hz));
    __nv_bfloat16 lw = __float2bfloat16_rn(x.w - __bfloat162float(hw));
    hi.x = pack_bf2(hx, hy);  hi.y = pack_bf2(hz, hw);
    lo.x = pack_bf2(lx, ly);  lo.y = pack_bf2(lz, lw);
}

__device__ __forceinline__ float4 h16_to_float4(uint2 p) {
    __half2 a = *reinterpret_cast<__half2*>(&p.x);
    __half2 b = *reinterpret_cast<__half2*>(&p.y);
    float2 f0 = __half22float2(a);
    float2 f1 = __half22float2(b);
    return make_float4(f0.x, f0.y, f1.x, f1.y);
}

// ---------------------------------------------------------------------------
// prep: zero counters + W fragments + fp16 gather table for h.
__global__ void prep_kernel(const float* __restrict__ h,
                            const float* __restrict__ Ws,
                            const float* __restrict__ Wn) {
    int idx = blockIdx.x * blockDim.x + threadIdx.x;
    if (idx < NODES) g_cnt[idx] = 0;
    if (idx == 0) g_nspill = 0;
    if (idx < 2 * 16 * NKS * 32 * 4) {
        int w    = idx & 3;
        int lane = (idx >> 2) & 31;
        int ks   = (idx >> 7) & 7;
        int nt   = (idx >> 10) & 15;
        int half = (idx >> 14) & 1;
        int p    = w >> 1;
        int reg  = w & 1;
        int n    = nt * 8 + (lane >> 2);
        int k    = ks * 16 + reg * 8 + 2 * (lane & 3);
        const float* W = half ? Wn : Ws;
        float w0 = W[n * D + k];
        float w1 = W[n * D + k + 1];
        __nv_bfloat16 h0 = __float2bfloat16_rn(w0);
        __nv_bfloat16 h1 = __float2bfloat16_rn(w1);
        __nv_bfloat16 v0, v1;
        if (p == 0) { v0 = h0; v1 = h1; }
        else {
            v0 = __float2bfloat16_rn(w0 - __bfloat162float(h0));
            v1 = __float2bfloat16_rn(w1 - __bfloat162float(h1));
        }
        reinterpret_cast<uint32_t*>(g_Wfrag)[idx] = pack_bf2(v0, v1);
    }
    if (idx < NODES * 32) {
        int node = idx >> 5;
        int q4   = idx & 31;
        float4 x = __ldg(reinterpret_cast<const float4*>(h + (size_t)node * D) + q4);
        __half2 p0 = __floats2half2_rn(x.x, x.y);
        __half2 p1 = __floats2half2_rn(x.z, x.w);
        uint2 o;
        o.x = *reinterpret_cast<uint32_t*>(&p0);
        o.y = *reinterpret_cast<uint32_t*>(&p1);
        g_h16[node * 32 + q4] = o;
    }
}

// ---------------------------------------------------------------------------
__global__ void scatter_kernel(const int*  __restrict__ row,
                               const int*  __restrict__ col,
                               const float* __restrict__ val,
                               int E) {
    int e = blockIdx.x * blockDim.x + threadIdx.x;
    if (e >= E) return;
    int r = row[e];
    int slot = atomicAdd(&g_cnt[r], 1);
    if (slot < CAP) {
        g_slots[r * CAP + slot] = make_int2(col[e], __float_as_int(val[e]));
    } else {
        int sp = atomicAdd(&g_nspill, 1);
        if (sp < SPILL_MAX)
            g_spill[sp] = make_int4(r, col[e], __float_as_int(val[e]), 0);
    }
}

// ---------------------------------------------------------------------------
// Bucketed SpMM: one warp per row; gathers fp16 h (half traffic);
// writes bf16-split packed support.
__global__ __launch_bounds__(256)
void spmm_kernel() {
    int gw   = (blockIdx.x * blockDim.x + threadIdx.x) >> 5;
    int lane = threadIdx.x & 31;
    if (gw >= NODES) return;

    int cnt0 = g_cnt[gw];
    bool over = cnt0 > CAP;
    int cnt = over ? CAP : cnt0;
    int beg = gw * CAP;
    int end = beg + cnt;

    float4 acc = make_float4(0.f, 0.f, 0.f, 0.f);
    int  e  = beg;
    int2 cv = (e < end) ? __ldg(&g_slots[e]) : make_int2(0, 0);
    while (e < end) {
        int2 cur = cv;
        if (e + 1 < end) cv = __ldg(&g_slots[e + 1]);
        float  v = __int_as_float(cur.y);
        float4 x = h16_to_float4(__ldg(&g_h16[cur.x * 32 + lane]));
        acc.x = fmaf(v, x.x, acc.x);
        acc.y = fmaf(v, x.y, acc.y);
        acc.z = fmaf(v, x.z, acc.z);
        acc.w = fmaf(v, x.w, acc.w);
        e++;
    }
    if (over) {
        int n = g_nspill; if (n > SPILL_MAX) n = SPILL_MAX;
        for (int i = 0; i < n; i++) {
            int4 s = g_spill[i];
            if (s.x == gw) {
                float v = __int_as_float(s.z);
                float4 x = h16_to_float4(__ldg(&g_h16[s.y * 32 + lane]));
                acc.x = fmaf(v, x.x, acc.x);
                acc.y = fmaf(v, x.y, acc.y);
                acc.z = fmaf(v, x.z, acc.z);
                acc.w = fmaf(v, x.w, acc.w);
            }
        }
    }
    uint2 hi, lo;
    split_packs(acc, hi, lo);
    reinterpret_cast<uint2*>(g_shi)[gw * 32 + lane] = hi;
    reinterpret_cast<uint2*>(g_slo)[gw * 32 + lane] = lo;
}

// ---------------------------------------------------------------------------
// Tensor-core fused GEMM (bf16x3 split via mma.sync) + concat + ReLU + LN.
// 64 nodes/CTA, 8 warps with m-group pairing (B fragments reused 6x).
// h staged from the fp16 table (L2-hot; bf16 hi/lo represents fp16 exactly).
__global__ __launch_bounds__(256, 2)
void gemm_ln_tc_kernel(const float* __restrict__ b_self,
                       const float* __restrict__ b_neigh,
                       const float* __restrict__ gamma,
                       const float* __restrict__ beta,
                       float* __restrict__ out) {
    extern __shared__ uint32_t sX[];        // tiles: 0=h_hi 1=h_lo 2=s_hi 3=s_lo
    __shared__ float sSum[4][64];           // [half*2+ntbI][row]
    __shared__ float sSq[4][64];
    __shared__ float sMu[64], sRs[64];

    const int tid   = threadIdx.x;
    const int node0 = blockIdx.x * MTILE;

    // Stage h (fp16 table, L2-hot) -> bf16 hi/lo tiles. 2048 uint2, 8/thread.
    #pragma unroll
    for (int it = 0; it < 8; it++) {
        int i   = tid + it * 256;
        int row = i >> 5, q4 = i & 31;
        int gn  = node0 + row;
        uint2 p = make_uint2(0u, 0u);
        if (gn < NODES) p = __ldg(&g_h16[gn * 32 + q4]);
        uint2 hi, lo;
        split_packs(h16_to_float4(p), hi, lo);
        *reinterpret_cast<uint2*>(sX + 0 * XT64_W + row * XROW_W + 2 * q4) = hi;
        *reinterpret_cast<uint2*>(sX + 1 * XT64_W + row * XROW_W + 2 * q4) = lo;
    }
    // Stage support (pre-split, L2-hot) -> pure uint4 copies. 2048, 8/thread.
    #pragma unroll
    for (int it = 0; it < 8; it++) {
        int i    = tid + it * 256;
        int tile = i >> 10;         // 0..1
        int rem  = i & 1023;
        int row  = rem >> 4, u4 = rem & 15;
        int gn   = node0 + row;
        uint4 v = make_uint4(0u, 0u, 0u, 0u);
        if (gn < NODES)
            v = __ldg(reinterpret_cast<const uint4*>(tile ? g_slo : g_shi) + gn * 16 + u4);
        *reinterpret_cast<uint4*>(sX + (2 + tile) * XT64_W + row * XROW_W + u4 * 4) = v;
    }
    __syncthreads();

    const int wid  = tid >> 5;
    const int lane = tid & 31;
    const int half = wid >> 2;
    const int ntbI = (wid >> 1) & 1;
    const int ntb  = ntbI * 8;
    const int mgp  = wid & 1;
    const int mr0  = mgp * 32;
    const int gr   = lane >> 2;
    const int q    = lane & 3;

    float acc[2][8][4];
    #pragma unroll
    for (int mg = 0; mg < 2; mg++)
        #pragma unroll
        for (int nt = 0; nt < 8; nt++)
            acc[mg][nt][0] = acc[mg][nt][1] = acc[mg][nt][2] = acc[mg][nt][3] = 0.f;

    const uint32_t* aHi0 = sX + (half * 2 + 0) * XT64_W + (mr0 + gr) * XROW_W + q;
    const uint32_t* aLo0 = sX + (half * 2 + 1) * XT64_W + (mr0 + gr) * XROW_W + q;
    const uint32_t* aHi1 = aHi0 + 16 * XROW_W;
    const uint32_t* aLo1 = aLo0 + 16 * XROW_W;
    const uint4* bBase = g_Wfrag + half * (16 * NKS * 32) + ntb * (NKS * 32) + lane;

    #pragma unroll
    for (int ks = 0; ks < NKS; ks++) {
        const int ko = ks * 8;
        uint32_t a0h0 = aHi0[ko],     a1h0 = aHi0[ko + 8 * XROW_W];
        uint32_t a2h0 = aHi0[ko + 4], a3h0 = aHi0[ko + 4 + 8 * XROW_W];
        uint32_t a0l0 = aLo0[ko],     a1l0 = aLo0[ko + 8 * XROW_W];
        uint32_t a2l0 = aLo0[ko + 4], a3l0 = aLo0[ko + 4 + 8 * XROW_W];
        uint32_t a0h1 = aHi1[ko],     a1h1 = aHi1[ko + 8 * XROW_W];
        uint32_t a2h1 = aHi1[ko + 4], a3h1 = aHi1[ko + 4 + 8 * XROW_W];
        uint32_t a0l1 = aLo1[ko],     a1l1 = aLo1[ko + 8 * XROW_W];
        uint32_t a2l1 = aLo1[ko + 4], a3l1 = aLo1[ko + 4 + 8 * XROW_W];
        const uint4* bp = bBase + ks * 32;
        #pragma unroll
        for (int nt = 0; nt < 8; nt++) {
            uint4 b = __ldg(bp + nt * (NKS * 32));
            mma_bf16(acc[0][nt][0], acc[0][nt][1], acc[0][nt][2], acc[0][nt][3],
                     a0h0, a1h0, a2h0, a3h0, b.x, b.y);
            mma_bf16(acc[0][nt][0], acc[0][nt][1], acc[0][nt][2], acc[0][nt][3],
                     a0h0, a1h0, a2h0, a3h0, b.z, b.w);
            mma_bf16(acc[0][nt][0], acc[0][nt][1], acc[0][nt][2], acc[0][nt][3],
                     a0l0, a1l0, a2l0, a3l0, b.x, b.y);
            mma_bf16(acc[1][nt][0], acc[1][nt][1], acc[1][nt][2], acc[1][nt][3],
                     a0h1, a1h1, a2h1, a3h1, b.x, b.y);
            mma_bf16(acc[1][nt][0], acc[1][nt][1], acc[1][nt][2], acc[1][nt][3],
                     a0h1, a1h1, a2h1, a3h1, b.z, b.w);
            mma_bf16(acc[1][nt][0], acc[1][nt][1], acc[1][nt][2], acc[1][nt][3],
                     a0l1, a1l1, a2l1, a3l1, b.x, b.y);
        }
    }

    // Epilogue: bias + ReLU, row partial stats (per m-group)
    const float2* bb = reinterpret_cast<const float2*>(half ? b_neigh : b_self);
    #pragma unroll
    for (int mg = 0; mg < 2; mg++) {
        float sA = 0.f, qA = 0.f, sB = 0.f, qB = 0.f;
        #pragma unroll
        for (int nt = 0; nt < 8; nt++) {
            float2 bv = __ldg(bb + (ntb + nt) * 4 + q);
            float v0 = fmaxf(acc[mg][nt][0] + bv.x, 0.f);
            float v1 = fmaxf(acc[mg][nt][1] + bv.y, 0.f);
            float v2 = fmaxf(acc[mg][nt][2] + bv.x, 0.f);
            float v3 = fmaxf(acc[mg][nt][3] + bv.y, 0.f);
            acc[mg][nt][0] = v0; acc[mg][nt][1] = v1;
            acc[mg][nt][2] = v2; acc[mg][nt][3] = v3;
            sA += v0 + v1;  qA += v0 * v0 + v1 * v1;
            sB += v2 + v3;  qB += v2 * v2 + v3 * v3;
        }
        #pragma unroll
        for (int o = 1; o <= 2; o <<= 1) {
            sA += __shfl_xor_sync(0xffffffffu, sA, o);
            qA += __shfl_xor_sync(0xffffffffu, qA, o);
            sB += __shfl_xor_sync(0xffffffffu, sB, o);
            qB += __shfl_xor_sync(0xffffffffu, qB, o);
        }
        if (q == 0) {
            int r0 = mr0 + mg * 16 + gr;
            sSum[half * 2 + ntbI][r0]     = sA;  sSq[half * 2 + ntbI][r0]     = qA;
            sSum[half * 2 + ntbI][r0 + 8] = sB;  sSq[half * 2 + ntbI][r0 + 8] = qB;
        }
    }
    __syncthreads();

    if (tid < 64) {
        float s  = sSum[0][tid] + sSum[1][tid] + sSum[2][tid] + sSum[3][tid];
        float sq = sSq[0][tid] + sSq[1][tid] + sSq[2][tid] + sSq[3][tid];
        float mu  = s * (1.f / 256.f);
        float var = sq * (1.f / 256.f) - mu * mu;
        sMu[tid] = mu;
        sRs[tid] = rsqrtf(var + LN_EPS);
    }
    __syncthreads();

    const float2* gg = reinterpret_cast<const float2*>(gamma) + half * 64;
    const float2* ee = reinterpret_cast<const float2*>(beta)  + half * 64;
    #pragma unroll
    for (int mg = 0; mg < 2; mg++) {
        int rowA = mr0 + mg * 16 + gr;
        int rowB = rowA + 8;
        float muA = sMu[rowA], rsA = sRs[rowA];
        float muB = sMu[rowB], rsB = sRs[rowB];
        int gnA = node0 + rowA;
        int gnB = node0 + rowB;
        #pragma unroll
        for (int nt = 0; nt < 8; nt++) {
            float2 gv = __ldg(gg + (ntb + nt) * 4 + q);
            float2 ev = __ldg(ee + (ntb + nt) * 4 + q);
            int coff = half * 128 + (ntb + nt) * 8 + 2 * q;
            if (gnA < NODES) {
                float2 o;
                o.x = (acc[mg][nt][0] - muA) * rsA * gv.x + ev.x;
                o.y = (acc[mg][nt][1] - muA) * rsA * gv.y + ev.y;
                *reinterpret_cast<float2*>(out + (size_t)gnA * DO2 + coff) = o;
            }
            if (gnB < NODES) {
                float2 o;
                o.x = (acc[mg][nt][2] - muB) * rsB * gv.x + ev.x;
                o.y = (acc[mg][nt][3] - muB) * rsB * gv.y + ev.y;
                *reinterpret_cast<float2*>(out + (size_t)gnB * DO2 + coff) = o;
            }
        }
    }
}

// ---------------------------------------------------------------------------
extern "C" void kernel_launch(void* const* d_in, const int* in_sizes, int n_in,
                              void* d_out, int out_size) {
    const float* h        = (const float*)d_in[0];
    const int*   edge_row = (const int*)  d_in[1];
    const int*   edge_col = (const int*)  d_in[2];
    const float* edge_val = (const float*)d_in[3];
    const float* W_self   = (const float*)d_in[4];
    const float* b_self   = (const float*)d_in[5];
    const float* W_neigh  = (const float*)d_in[6];
    const float* b_neigh  = (const float*)d_in[7];
    const float* ln_gamma = (const float*)d_in[8];
    const float* ln_beta  = (const float*)d_in[9];
    float*       out      = (float*)d_out;

    const int E  = in_sizes[1];
    const int eb = (E + 255) / 256;

    static bool attr_done = false;
    if (!attr_done) {
        cudaFuncSetAttribute(gemm_ln_tc_kernel,
                             cudaFuncAttributeMaxDynamicSharedMemorySize, SMEM_GEMM);
        attr_done = true;
    }

    prep_kernel<<<(NODES * 32 + 255) / 256, 256>>>(h, W_self, W_neigh);
    scatter_kernel<<<eb, 256>>>(edge_row, edge_col, edge_val, E);
    spmm_kernel<<<(NODES * 32 + 255) / 256, 256>>>();
    gemm_ln_tc_kernel<<<GRID_G, 256, SMEM_GEMM>>>(b_self, b_neigh,
                                                  ln_gamma, ln_beta, out);
}

// round 16
// speedup vs baseline: 1.0152x; 1.0152x over previous
#include <cuda_runtime.h>
#include <cuda_bf16.h>
#include <cstdint>

#define D      128
#define DO2    256
#define NODES  50000
#define LN_EPS 1e-5f

#define CAP    64
#define SPILL_MAX 8192

#define MTILE  64
#define GRID_G ((NODES + MTILE - 1) / MTILE) // 782

#define XROW_W 68
#define XT64_W (64 * XROW_W)            // 4352 words per tile
#define SMEM_GEMM (4 * XT64_W * 4)      // 69632 bytes

#define NKS    8

// Scratch
__device__ int      g_cnt[NODES];
__device__ int2     g_slots[NODES * CAP];
__device__ int4     g_spill[SPILL_MAX];
__device__ int      g_nspill;
// support in bf16 hi/lo packed form (written by spmm, L2-hot for gemm)
__device__ uint32_t g_shi[NODES * 64];
__device__ uint32_t g_slo[NODES * 64];
// W fragments, LDG.128-packed: uint4[half][nt(16)][ks(8)][lane(32)]
__device__ uint4    g_Wfrag[2 * 16 * NKS * 32];

// ---------------------------------------------------------------------------
__device__ __forceinline__ uint32_t pack_bf2(__nv_bfloat16 lo, __nv_bfloat16 hi) {
    return (uint32_t)__bfloat16_as_ushort(hi) << 16 | (uint32_t)__bfloat16_as_ushort(lo);
}

__device__ __forceinline__ void mma_bf16(float& d0, float& d1, float& d2, float& d3,
                                         uint32_t a0, uint32_t a1, uint32_t a2, uint32_t a3,
                                         uint32_t b0, uint32_t b1) {
    asm volatile(
        "mma.sync.aligned.m16n8k16.row.col.f32.bf16.bf16.f32 "
        "{%0,%1,%2,%3}, {%4,%5,%6,%7}, {%8,%9}, {%0,%1,%2,%3};"
        : "+f"(d0), "+f"(d1), "+f"(d2), "+f"(d3)
        : "r"(a0), "r"(a1), "r"(a2), "r"(a3), "r"(b0), "r"(b1));
}

__device__ __forceinline__ void split_packs(float4 x, uint2& hi, uint2& lo) {
    __nv_bfloat16 hx = __float2bfloat16_rn(x.x);
    __nv_bfloat16 hy = __float2bfloat16_rn(x.y);
    __nv_bfloat16 hz = __float2bfloat16_rn(x.z);
    __nv_bfloat16 hw = __float2bfloat16_rn(x.w);
    __nv_bfloat16 lx = __float2bfloat16_rn(x.x - __bfloat162float(hx));
    __nv_bfloat16 ly = __float2bfloat16_rn(x.y - __bfloat162float(hy));
    __nv_bfloat16 lz = __float2bfloat16_rn(x.z - __bfloat162float(hz));
    __nv_bfloat16 lw = __float2bfloat16_rn(x.w - __bfloat162float(hw));
    hi.x = pack_bf2(hx, hy);  hi.y = pack_bf2(hz, hw);
    lo.x = pack_bf2(lx, ly);  lo.y = pack_bf2(lz, lw);
}

// ---------------------------------------------------------------------------
// prep: zero counters + build packed bf16-split W fragments.
__global__ void prep_kernel(const float* __restrict__ Ws,
                            const float* __restrict__ Wn) {
    int idx = blockIdx.x * blockDim.x + threadIdx.x;
    if (idx < NODES) g_cnt[idx] = 0;
    if (idx == 0) g_nspill = 0;
    if (idx < 2 * 16 * NKS * 32 * 4) {
        int w    = idx & 3;
        int lane = (idx >> 2) & 31;
        int ks   = (idx >> 7) & 7;
        int nt   = (idx >> 10) & 15;
        int half = (idx >> 14) & 1;
        int p    = w >> 1;
        int reg  = w & 1;
        int n    = nt * 8 + (lane >> 2);
        int k    = ks * 16 + reg * 8 + 2 * (lane & 3);
        const float* W = half ? Wn : Ws;
        float w0 = W[n * D + k];
        float w1 = W[n * D + k + 1];
        __nv_bfloat16 h0 = __float2bfloat16_rn(w0);
        __nv_bfloat16 h1 = __float2bfloat16_rn(w1);
        __nv_bfloat16 v0, v1;
        if (p == 0) { v0 = h0; v1 = h1; }
        else {
            v0 = __float2bfloat16_rn(w0 - __bfloat162float(h0));
            v1 = __float2bfloat16_rn(w1 - __bfloat162float(h1));
        }
        reinterpret_cast<uint32_t*>(g_Wfrag)[idx] = pack_bf2(v0, v1);
    }
}

// ---------------------------------------------------------------------------
__global__ void scatter_kernel(const int*  __restrict__ row,
                               const int*  __restrict__ col,
                               const float* __restrict__ val,
                               int E) {
    int e = blockIdx.x * blockDim.x + threadIdx.x;
    if (e >= E) return;
    int r = row[e];
    int slot = atomicAdd(&g_cnt[r], 1);
    if (slot < CAP) {
        g_slots[r * CAP + slot] = make_int2(col[e], __float_as_int(val[e]));
    } else {
        int sp = atomicAdd(&g_nspill, 1);
        if (sp < SPILL_MAX)
            g_spill[sp] = make_int4(r, col[e], __float_as_int(val[e]), 0);
    }
}

// ---------------------------------------------------------------------------
// Bucketed SpMM: one warp per row. Edge list loaded cooperatively into
// registers (2 LDGs), broadcast per-edge via shuffle -> every gather LDG is
// address-independent; 4x unroll sustains MLP>=4.
__global__ __launch_bounds__(256)
void spmm_kernel(const float* __restrict__ h) {
    int gw   = (blockIdx.x * blockDim.x + threadIdx.x) >> 5;
    int lane = threadIdx.x & 31;
    if (gw >= NODES) return;

    int cnt0 = g_cnt[gw];
    bool over = cnt0 > CAP;
    int cnt = over ? CAP : cnt0;

    // Cooperative slot load: lane l holds slots l and 32+l
    int2 e0 = __ldg(&g_slots[gw * CAP + lane]);
    int2 e1 = __ldg(&g_slots[gw * CAP + 32 + lane]);

    float4 acc = make_float4(0.f, 0.f, 0.f, 0.f);
    const float4* hb = reinterpret_cast<const float4*>(h) + lane;

    int e = 0;
    for (; e + 4 <= cnt; e += 4) {
        int2 s0 = (e + 0 < 32) ? e0 : e1;
        int2 s1 = (e + 1 < 32) ? e0 : e1;
        int2 s2 = (e + 2 < 32) ? e0 : e1;
        int2 s3 = (e + 3 < 32) ? e0 : e1;
        int c0 = __shfl_sync(0xffffffffu, s0.x, (e + 0) & 31);
        int v0 = __shfl_sync(0xffffffffu, s0.y, (e + 0) & 31);
        int c1 = __shfl_sync(0xffffffffu, s1.x, (e + 1) & 31);
        int v1 = __shfl_sync(0xffffffffu, s1.y, (e + 1) & 31);
        int c2 = __shfl_sync(0xffffffffu, s2.x, (e + 2) & 31);
        int v2 = __shfl_sync(0xffffffffu, s2.y, (e + 2) & 31);
        int c3 = __shfl_sync(0xffffffffu, s3.x, (e + 3) & 31);
        int v3 = __shfl_sync(0xffffffffu, s3.y, (e + 3) & 31);
        float4 x0 = __ldg(hb + (size_t)c0 * 32);
        float4 x1 = __ldg(hb + (size_t)c1 * 32);
        float4 x2 = __ldg(hb + (size_t)c2 * 32);
        float4 x3 = __ldg(hb + (size_t)c3 * 32);
        float f0 = __int_as_float(v0), f1 = __int_as_float(v1);
        float f2 = __int_as_float(v2), f3 = __int_as_float(v3);
        acc.x = fmaf(f0, x0.x, acc.x); acc.y = fmaf(f0, x0.y, acc.y);
        acc.z = fmaf(f0, x0.z, acc.z); acc.w = fmaf(f0, x0.w, acc.w);
        acc.x = fmaf(f1, x1.x, acc.x); acc.y = fmaf(f1, x1.y, acc.y);
        acc.z = fmaf(f1, x1.z, acc.z); acc.w = fmaf(f1, x1.w, acc.w);
        acc.x = fmaf(f2, x2.x, acc.x); acc.y = fmaf(f2, x2.y, acc.y);
        acc.z = fmaf(f2, x2.z, acc.z); acc.w = fmaf(f2, x2.w, acc.w);
        acc.x = fmaf(f3, x3.x, acc.x); acc.y = fmaf(f3, x3.y, acc.y);
        acc.z = fmaf(f3, x3.z, acc.z); acc.w = fmaf(f3, x3.w, acc.w);
    }
    for (; e < cnt; e++) {
        int2 s = (e < 32) ? e0 : e1;
        int c = __shfl_sync(0xffffffffu, s.x, e & 31);
        int v = __shfl_sync(0xffffffffu, s.y, e & 31);
        float4 x = __ldg(hb + (size_t)c * 32);
        float f = __int_as_float(v);
        acc.x = fmaf(f, x.x, acc.x); acc.y = fmaf(f, x.y, acc.y);
        acc.z = fmaf(f, x.z, acc.z); acc.w = fmaf(f, x.w, acc.w);
    }
    if (over) {
        int n = g_nspill; if (n > SPILL_MAX) n = SPILL_MAX;
        for (int i = 0; i < n; i++) {
            int4 s = g_spill[i];
            if (s.x == gw) {
                float v = __int_as_float(s.z);
                float4 x = __ldg(hb + (size_t)s.y * 32);
                acc.x = fmaf(v, x.x, acc.x);
                acc.y = fmaf(v, x.y, acc.y);
                acc.z = fmaf(v, x.z, acc.z);
                acc.w = fmaf(v, x.w, acc.w);
            }
        }
    }
    uint2 hi, lo;
    split_packs(acc, hi, lo);
    reinterpret_cast<uint2*>(g_shi)[gw * 32 + lane] = hi;
    reinterpret_cast<uint2*>(g_slo)[gw * 32 + lane] = lo;
}

// ---------------------------------------------------------------------------
// Tensor-core fused GEMM (bf16x3 split via mma.sync) + concat + ReLU + LN.
// 64 nodes/CTA, 8 warps with m-group pairing (B fragments reused 6x).
__global__ __launch_bounds__(256, 2)
void gemm_ln_tc_kernel(const float* __restrict__ h,
                       const float* __restrict__ b_self,
                       const float* __restrict__ b_neigh,
                       const float* __restrict__ gamma,
                       const float* __restrict__ beta,
                       float* __restrict__ out) {
    extern __shared__ uint32_t sX[];        // tiles: 0=h_hi 1=h_lo 2=s_hi 3=s_lo
    __shared__ float sSum[4][64];           // [half*2+ntbI][row]
    __shared__ float sSq[4][64];
    __shared__ float sMu[64], sRs[64];

    const int tid   = threadIdx.x;
    const int node0 = blockIdx.x * MTILE;

    // Stage h (fp32, L2-hot) -> bf16 hi/lo tiles. 2048 float4, 8/thread.
    #pragma unroll
    for (int it = 0; it < 8; it++) {
        int i   = tid + it * 256;
        int row = i >> 5, q4 = i & 31;
        int gn  = node0 + row;
        float4 x = (gn < NODES)
                 ? __ldg(reinterpret_cast<const float4*>(h + (size_t)gn * D) + q4)
                 : make_float4(0.f, 0.f, 0.f, 0.f);
        uint2 hi, lo;
        split_packs(x, hi, lo);
        *reinterpret_cast<uint2*>(sX + 0 * XT64_W + row * XROW_W + 2 * q4) = hi;
        *reinterpret_cast<uint2*>(sX + 1 * XT64_W + row * XROW_W + 2 * q4) = lo;
    }
    // Stage support (pre-split, L2-hot) -> pure uint4 copies. 2048, 8/thread.
    #pragma unroll
    for (int it = 0; it < 8; it++) {
        int i    = tid + it * 256;
        int tile = i >> 10;         // 0..1
        int rem  = i & 1023;
        int row  = rem >> 4, u4 = rem & 15;
        int gn   = node0 + row;
        uint4 v = make_uint4(0u, 0u, 0u, 0u);
        if (gn < NODES)
            v = __ldg(reinterpret_cast<const uint4*>(tile ? g_slo : g_shi) + gn * 16 + u4);
        *reinterpret_cast<uint4*>(sX + (2 + tile) * XT64_W + row * XROW_W + u4 * 4) = v;
    }
    __syncthreads();

    const int wid  = tid >> 5;
    const int lane = tid & 31;
    const int half = wid >> 2;
    const int ntbI = (wid >> 1) & 1;
    const int ntb  = ntbI * 8;
    const int mgp  = wid & 1;
    const int mr0  = mgp * 32;
    const int gr   = lane >> 2;
    const int q    = lane & 3;

    float acc[2][8][4];
    #pragma unroll
    for (int mg = 0; mg < 2; mg++)
        #pragma unroll
        for (int nt = 0; nt < 8; nt++)
            acc[mg][nt][0] = acc[mg][nt][1] = acc[mg][nt][2] = acc[mg][nt][3] = 0.f;

    const uint32_t* aHi0 = sX + (half * 2 + 0) * XT64_W + (mr0 + gr) * XROW_W + q;
    const uint32_t* aLo0 = sX + (half * 2 + 1) * XT64_W + (mr0 + gr) * XROW_W + q;
    const uint32_t* aHi1 = aHi0 + 16 * XROW_W;
    const uint32_t* aLo1 = aLo0 + 16 * XROW_W;
    const uint4* bBase = g_Wfrag + half * (16 * NKS * 32) + ntb * (NKS * 32) + lane;

    #pragma unroll
    for (int ks = 0; ks < NKS; ks++) {
        const int ko = ks * 8;
        uint32_t a0h0 = aHi0[ko],     a1h0 = aHi0[ko + 8 * XROW_W];
        uint32_t a2h0 = aHi0[ko + 4], a3h0 = aHi0[ko + 4 + 8 * XROW_W];
        uint32_t a0l0 = aLo0[ko],     a1l0 = aLo0[ko + 8 * XROW_W];
        uint32_t a2l0 = aLo0[ko + 4], a3l0 = aLo0[ko + 4 + 8 * XROW_W];
        uint32_t a0h1 = aHi1[ko],     a1h1 = aHi1[ko + 8 * XROW_W];
        uint32_t a2h1 = aHi1[ko + 4], a3h1 = aHi1[ko + 4 + 8 * XROW_W];
        uint32_t a0l1 = aLo1[ko],     a1l1 = aLo1[ko + 8 * XROW_W];
        uint32_t a2l1 = aLo1[ko + 4], a3l1 = aLo1[ko + 4 + 8 * XROW_W];
        const uint4* bp = bBase + ks * 32;
        #pragma unroll
        for (int nt = 0; nt < 8; nt++) {
            uint4 b = __ldg(bp + nt * (NKS * 32));
            mma_bf16(acc[0][nt][0], acc[0][nt][1], acc[0][nt][2], acc[0][nt][3],
                     a0h0, a1h0, a2h0, a3h0, b.x, b.y);
            mma_bf16(acc[0][nt][0], acc[0][nt][1], acc[0][nt][2], acc[0][nt][3],
                     a0h0, a1h0, a2h0, a3h0, b.z, b.w);
            mma_bf16(acc[0][nt][0], acc[0][nt][1], acc[0][nt][2], acc[0][nt][3],
                     a0l0, a1l0, a2l0, a3l0, b.x, b.y);
            mma_bf16(acc[1][nt][0], acc[1][nt][1], acc[1][nt][2], acc[1][nt][3],
                     a0h1, a1h1, a2h1, a3h1, b.x, b.y);
            mma_bf16(acc[1][nt][0], acc[1][nt][1], acc[1][nt][2], acc[1][nt][3],
                     a0h1, a1h1, a2h1, a3h1, b.z, b.w);
            mma_bf16(acc[1][nt][0], acc[1][nt][1], acc[1][nt][2], acc[1][nt][3],
                     a0l1, a1l1, a2l1, a3l1, b.x, b.y);
        }
    }

    // Epilogue: bias + ReLU, row partial stats (per m-group)
    const float2* bb = reinterpret_cast<const float2*>(half ? b_neigh : b_self);
    #pragma unroll
    for (int mg = 0; mg < 2; mg++) {
        float sA = 0.f, qA = 0.f, sB = 0.f, qB = 0.f;
        #pragma unroll
        for (int nt = 0; nt < 8; nt++) {
            float2 bv = __ldg(bb + (ntb + nt) * 4 + q);
            float v0 = fmaxf(acc[mg][nt][0] + bv.x, 0.f);
            float v1 = fmaxf(acc[mg][nt][1] + bv.y, 0.f);
            float v2 = fmaxf(acc[mg][nt][2] + bv.x, 0.f);
            float v3 = fmaxf(acc[mg][nt][3] + bv.y, 0.f);
            acc[mg][nt][0] = v0; acc[mg][nt][1] = v1;
            acc[mg][nt][2] = v2; acc[mg][nt][3] = v3;
            sA += v0 + v1;  qA += v0 * v0 + v1 * v1;
            sB += v2 + v3;  qB += v2 * v2 + v3 * v3;
        }
        #pragma unroll
        for (int o = 1; o <= 2; o <<= 1) {
            sA += __shfl_xor_sync(0xffffffffu, sA, o);
            qA += __shfl_xor_sync(0xffffffffu, qA, o);
            sB += __shfl_xor_sync(0xffffffffu, sB, o);
            qB += __shfl_xor_sync(0xffffffffu, qB, o);
        }
        if (q == 0) {
            int r0 = mr0 + mg * 16 + gr;
            sSum[half * 2 + ntbI][r0]     = sA;  sSq[half * 2 + ntbI][r0]     = qA;
            sSum[half * 2 + ntbI][r0 + 8] = sB;  sSq[half * 2 + ntbI][r0 + 8] = qB;
        }
    }
    __syncthreads();

    if (tid < 64) {
        float s  = sSum[0][tid] + sSum[1][tid] + sSum[2][tid] + sSum[3][tid];
        float sq = sSq[0][tid] + sSq[1][tid] + sSq[2][tid] + sSq[3][tid];
        float mu  = s * (1.f / 256.f);
        float var = sq * (1.f / 256.f) - mu * mu;
        sMu[tid] = mu;
        sRs[tid] = rsqrtf(var + LN_EPS);
    }
    __syncthreads();

    const float2* gg = reinterpret_cast<const float2*>(gamma) + half * 64;
    const float2* ee = reinterpret_cast<const float2*>(beta)  + half * 64;
    #pragma unroll
    for (int mg = 0; mg < 2; mg++) {
        int rowA = mr0 + mg * 16 + gr;
        int rowB = rowA + 8;
        float muA = sMu[rowA], rsA = sRs[rowA];
        float muB = sMu[rowB], rsB = sRs[rowB];
        int gnA = node0 + rowA;
        int gnB = node0 + rowB;
        #pragma unroll
        for (int nt = 0; nt < 8; nt++) {
            float2 gv = __ldg(gg + (ntb + nt) * 4 + q);
            float2 ev = __ldg(ee + (ntb + nt) * 4 + q);
            int coff = half * 128 + (ntb + nt) * 8 + 2 * q;
            if (gnA < NODES) {
                float2 o;
                o.x = (acc[mg][nt][0] - muA) * rsA * gv.x + ev.x;
                o.y = (acc[mg][nt][1] - muA) * rsA * gv.y + ev.y;
                *reinterpret_cast<float2*>(out + (size_t)gnA * DO2 + coff) = o;
            }
            if (gnB < NODES) {
                float2 o;
                o.x = (acc[mg][nt][2] - muB) * rsB * gv.x + ev.x;
                o.y = (acc[mg][nt][3] - muB) * rsB * gv.y + ev.y;
                *reinterpret_cast<float2*>(out + (size_t)gnB * DO2 + coff) = o;
            }
        }
    }
}

// ---------------------------------------------------------------------------
extern "C" void kernel_launch(void* const* d_in, const int* in_sizes, int n_in,
                              void* d_out, int out_size) {
    const float* h        = (const float*)d_in[0];
    const int*   edge_row = (const int*)  d_in[1];
    const int*   edge_col = (const int*)  d_in[2];
    const float* edge_val = (const float*)d_in[3];
    const float* W_self   = (const float*)d_in[4];
    const float* b_self   = (const float*)d_in[5];
    const float* W_neigh  = (const float*)d_in[6];
    const float* b_neigh  = (const float*)d_in[7];
    const float* ln_gamma = (const float*)d_in[8];
    const float* ln_beta  = (const float*)d_in[9];
    float*       out      = (float*)d_out;

    const int E  = in_sizes[1];
    const int eb = (E + 255) / 256;

    static bool attr_done = false;
    if (!attr_done) {
        cudaFuncSetAttribute(gemm_ln_tc_kernel,
                             cudaFuncAttributeMaxDynamicSharedMemorySize, SMEM_GEMM);
        attr_done = true;
    }

    prep_kernel<<<196, 256>>>(W_self, W_neigh);
    scatter_kernel<<<eb, 256>>>(edge_row, edge_col, edge_val, E);
    spmm_kernel<<<(NODES * 32 + 255) / 256, 256>>>(h);
    gemm_ln_tc_kernel<<<GRID_G, 256, SMEM_GEMM>>>(h, b_self, b_neigh,
                                                  ln_gamma, ln_beta, out);
}